// round 1
// baseline (speedup 1.0000x reference)
#include <cuda_runtime.h>
#include <math.h>

// ---------------------------------------------------------------------------
// PhaseQuantizer: 2-step residual phase quantization.
//   per step: global masked abs-means (s_re, s_im) -> soft 4-center softmax
//   over wrapped phase deltas -> q = (p0-p2)*s_re, (p1-p3)*s_im.
// Kernel plan (3 big passes + 2 tiny reduces, all graph-capturable):
//   k_stats1 -> k_reduce(0) -> k_step2 -> k_reduce(2) -> k_final
// ---------------------------------------------------------------------------

namespace {
constexpr int NBLK = 1184;   // 8 blocks/SM on 148 SMs
constexpr int NTHR = 256;
constexpr float PI_F = 3.14159265358979323846f;
}

struct Part { float sre, sim; int cre, cim; };
__device__ Part  g_part[NBLK];
__device__ float g_scale[4];   // s_re1, s_im1, s_re2, s_im2

// atan(x) for |x|<=1, Abramowitz & Stegun 4.4.49, |err| <= 1e-5 rad
__device__ __forceinline__ float atan_unit(float r) {
    float r2 = r * r;
    float p = fmaf(r2,  0.0208351f, -0.0851330f);
    p = fmaf(r2, p,  0.1801410f);
    p = fmaf(r2, p, -0.3302995f);
    p = fmaf(r2, p,  0.9998660f);
    return r * p;
}

// One quantization eval. kB = pi/t, c1 = exp(-pi^2/(4t)), c3 = c1^4.
// Softmax over centers {0, pi/2, pi, -pi/2} with the nearest-center logit
// factored out (identical to jax.nn.softmax's max-subtraction).
__device__ __forceinline__ void quant_eval(float re, float im,
                                           float sre, float sim,
                                           float kB, float c1, float c3,
                                           float& qre, float& qim) {
    float ar = fabsf(re), ai = fabsf(im);
    bool  rd = (ar >= ai);                 // real-axis dominant
    float major = rd ? re : im;
    float minor = rd ? im : re;
    float r = (major == 0.0f) ? 0.0f : __fdividef(minor, major);
    float psi = atan_unit(r);              // angle to nearest center
    psi = rd ? psi : -psi;                 // imag-dominant: psi = -atan(re/im)
    float wv  = kB * psi;
    float B   = __expf(wv);
    float Bi  = __expf(-wv);
    float Bs  = (psi >= 0.0f) ? B : Bi;    // e^{pi*|psi|/t}
    float uo  = c3 * Bs * Bs;              // opposite-center weight
    float D   = fmaf(c1, B + Bi, 1.0f + uo);
    float invD = __fdividef(1.0f, D);
    float P = (1.0f - uo) * invD;          // p_near - p_opp
    float Q = c1 * (B - Bi) * invD;        // p_+90 - p_-90
    if (rd) {
        float s = copysignf(1.0f, re);
        qre = s * P * sre;
        qim = s * Q * sim;
    } else {
        float s = copysignf(1.0f, im);
        qim = s * P * sim;
        qre = -s * Q * sre;
    }
}

__device__ __forceinline__ void acc_stats(float re, float im,
                                          float& sre, float& sim,
                                          int& cre, int& cim) {
    float ar = fabsf(re), ai = fabsf(im);
    if (ar >= ai) { sre += ar; cre++; }
    else          { sim += ai; cim++; }
}

// Deterministic fixed-order block reduce -> per-block partial slot.
__device__ __forceinline__ void stats_reduce_store(float sre, float sim,
                                                   int cre, int cim) {
    #pragma unroll
    for (int o = 16; o > 0; o >>= 1) {
        sre += __shfl_down_sync(0xffffffffu, sre, o);
        sim += __shfl_down_sync(0xffffffffu, sim, o);
        cre += __shfl_down_sync(0xffffffffu, cre, o);
        cim += __shfl_down_sync(0xffffffffu, cim, o);
    }
    __shared__ float sh_sre[NTHR / 32], sh_sim[NTHR / 32];
    __shared__ int   sh_cre[NTHR / 32], sh_cim[NTHR / 32];
    int lane = threadIdx.x & 31, wrp = threadIdx.x >> 5;
    if (lane == 0) { sh_sre[wrp] = sre; sh_sim[wrp] = sim;
                     sh_cre[wrp] = cre; sh_cim[wrp] = cim; }
    __syncthreads();
    if (threadIdx.x == 0) {
        float a = 0.f, b = 0.f; int c = 0, d = 0;
        #pragma unroll
        for (int i = 0; i < NTHR / 32; i++) {
            a += sh_sre[i]; b += sh_sim[i]; c += sh_cre[i]; d += sh_cim[i];
        }
        g_part[blockIdx.x].sre = a; g_part[blockIdx.x].sim = b;
        g_part[blockIdx.x].cre = c; g_part[blockIdx.x].cim = d;
    }
}

// Pass 1: masked abs-sums of raw w.
__global__ void __launch_bounds__(NTHR)
k_stats1(const float* __restrict__ re, const float* __restrict__ im, int n) {
    float sre = 0.f, sim = 0.f; int cre = 0, cim = 0;
    int gtid = blockIdx.x * blockDim.x + threadIdx.x;
    int stride = gridDim.x * blockDim.x;
    int n4 = n >> 2;
    const float4* re4 = reinterpret_cast<const float4*>(re);
    const float4* im4 = reinterpret_cast<const float4*>(im);
    for (int i = gtid; i < n4; i += stride) {
        float4 a = re4[i], b = im4[i];
        acc_stats(a.x, b.x, sre, sim, cre, cim);
        acc_stats(a.y, b.y, sre, sim, cre, cim);
        acc_stats(a.z, b.z, sre, sim, cre, cim);
        acc_stats(a.w, b.w, sre, sim, cre, cim);
    }
    for (int i = (n4 << 2) + gtid; i < n; i += stride)
        acc_stats(re[i], im[i], sre, sim, cre, cim);
    stats_reduce_store(sre, sim, cre, cim);
}

// Tiny deterministic final reduce: g_part -> g_scale[off], g_scale[off+1].
__global__ void __launch_bounds__(NTHR)
k_reduce(int off) {
    float sre = 0.f, sim = 0.f; int cre = 0, cim = 0;
    for (int i = threadIdx.x; i < NBLK; i += blockDim.x) {
        Part p = g_part[i];
        sre += p.sre; sim += p.sim; cre += p.cre; cim += p.cim;
    }
    #pragma unroll
    for (int o = 16; o > 0; o >>= 1) {
        sre += __shfl_down_sync(0xffffffffu, sre, o);
        sim += __shfl_down_sync(0xffffffffu, sim, o);
        cre += __shfl_down_sync(0xffffffffu, cre, o);
        cim += __shfl_down_sync(0xffffffffu, cim, o);
    }
    __shared__ float sh_sre[NTHR / 32], sh_sim[NTHR / 32];
    __shared__ int   sh_cre[NTHR / 32], sh_cim[NTHR / 32];
    int lane = threadIdx.x & 31, wrp = threadIdx.x >> 5;
    if (lane == 0) { sh_sre[wrp] = sre; sh_sim[wrp] = sim;
                     sh_cre[wrp] = cre; sh_cim[wrp] = cim; }
    __syncthreads();
    if (threadIdx.x == 0) {
        float a = 0.f, b = 0.f; int c = 0, d = 0;
        #pragma unroll
        for (int i = 0; i < NTHR / 32; i++) {
            a += sh_sre[i]; b += sh_sim[i]; c += sh_cre[i]; d += sh_cim[i];
        }
        // s = max(sum / max(cnt,1), 1e-6); cnt==0 => sum==0 => clamp to 1e-6
        g_scale[off]     = fmaxf(a / fmaxf((float)c, 1.0f), 1e-6f);
        g_scale[off + 1] = fmaxf(b / fmaxf((float)d, 1.0f), 1e-6f);
    }
}

// Pass 2: compute q1 from s1, accumulate stats of err1 = w - q1. No writes.
__global__ void __launch_bounds__(NTHR)
k_step2(const float* __restrict__ re, const float* __restrict__ im,
        const float* __restrict__ temp, int n) {
    float t = *temp + 1e-6f;
    float inv_t = __fdividef(1.0f, t);
    float kB = PI_F * inv_t;
    float c1 = __expf(-(PI_F * PI_F * 0.25f) * inv_t);
    float c3 = c1 * c1; c3 = c3 * c3;
    float s1re = g_scale[0], s1im = g_scale[1];

    float sre = 0.f, sim = 0.f; int cre = 0, cim = 0;
    int gtid = blockIdx.x * blockDim.x + threadIdx.x;
    int stride = gridDim.x * blockDim.x;
    int n4 = n >> 2;
    const float4* re4 = reinterpret_cast<const float4*>(re);
    const float4* im4 = reinterpret_cast<const float4*>(im);
    for (int i = gtid; i < n4; i += stride) {
        float4 a = re4[i], b = im4[i];
        float qr, qi;
        quant_eval(a.x, b.x, s1re, s1im, kB, c1, c3, qr, qi);
        acc_stats(a.x - qr, b.x - qi, sre, sim, cre, cim);
        quant_eval(a.y, b.y, s1re, s1im, kB, c1, c3, qr, qi);
        acc_stats(a.y - qr, b.y - qi, sre, sim, cre, cim);
        quant_eval(a.z, b.z, s1re, s1im, kB, c1, c3, qr, qi);
        acc_stats(a.z - qr, b.z - qi, sre, sim, cre, cim);
        quant_eval(a.w, b.w, s1re, s1im, kB, c1, c3, qr, qi);
        acc_stats(a.w - qr, b.w - qi, sre, sim, cre, cim);
    }
    for (int i = (n4 << 2) + gtid; i < n; i += stride) {
        float qr, qi;
        quant_eval(re[i], im[i], s1re, s1im, kB, c1, c3, qr, qi);
        acc_stats(re[i] - qr, im[i] - qi, sre, sim, cre, cim);
    }
    stats_reduce_store(sre, sim, cre, cim);
}

// Pass 3: recompute q1, err1, compute q2, write qw = q1 + q2.
__global__ void __launch_bounds__(NTHR)
k_final(const float* __restrict__ re, const float* __restrict__ im,
        const float* __restrict__ temp,
        float* __restrict__ out_re, float* __restrict__ out_im, int n) {
    float t = *temp + 1e-6f;
    float inv_t = __fdividef(1.0f, t);
    float kB = PI_F * inv_t;
    float c1 = __expf(-(PI_F * PI_F * 0.25f) * inv_t);
    float c3 = c1 * c1; c3 = c3 * c3;
    float s1re = g_scale[0], s1im = g_scale[1];
    float s2re = g_scale[2], s2im = g_scale[3];

    int gtid = blockIdx.x * blockDim.x + threadIdx.x;
    int stride = gridDim.x * blockDim.x;

    if ((n & 3) == 0) {
        int n4 = n >> 2;
        const float4* re4 = reinterpret_cast<const float4*>(re);
        const float4* im4 = reinterpret_cast<const float4*>(im);
        float4* or4 = reinterpret_cast<float4*>(out_re);
        float4* oi4 = reinterpret_cast<float4*>(out_im);
        for (int i = gtid; i < n4; i += stride) {
            float4 a = re4[i], b = im4[i];
            float4 qr4, qi4;
            {
                float q1r, q1i, q2r, q2i;
                quant_eval(a.x, b.x, s1re, s1im, kB, c1, c3, q1r, q1i);
                quant_eval(a.x - q1r, b.x - q1i, s2re, s2im, kB, c1, c3, q2r, q2i);
                qr4.x = q1r + q2r; qi4.x = q1i + q2i;
                quant_eval(a.y, b.y, s1re, s1im, kB, c1, c3, q1r, q1i);
                quant_eval(a.y - q1r, b.y - q1i, s2re, s2im, kB, c1, c3, q2r, q2i);
                qr4.y = q1r + q2r; qi4.y = q1i + q2i;
                quant_eval(a.z, b.z, s1re, s1im, kB, c1, c3, q1r, q1i);
                quant_eval(a.z - q1r, b.z - q1i, s2re, s2im, kB, c1, c3, q2r, q2i);
                qr4.z = q1r + q2r; qi4.z = q1i + q2i;
                quant_eval(a.w, b.w, s1re, s1im, kB, c1, c3, q1r, q1i);
                quant_eval(a.w - q1r, b.w - q1i, s2re, s2im, kB, c1, c3, q2r, q2i);
                qr4.w = q1r + q2r; qi4.w = q1i + q2i;
            }
            or4[i] = qr4;
            oi4[i] = qi4;
        }
    } else {
        for (int i = gtid; i < n; i += stride) {
            float q1r, q1i, q2r, q2i;
            quant_eval(re[i], im[i], s1re, s1im, kB, c1, c3, q1r, q1i);
            quant_eval(re[i] - q1r, im[i] - q1i, s2re, s2im, kB, c1, c3, q2r, q2i);
            out_re[i] = q1r + q2r;
            out_im[i] = q1i + q2i;
        }
    }
}

extern "C" void kernel_launch(void* const* d_in, const int* in_sizes, int n_in,
                              void* d_out, int out_size) {
    const float* w_re = (const float*)d_in[0];
    const float* w_im = (const float*)d_in[1];
    const float* temp = (const float*)d_in[2];
    int n = in_sizes[0];
    float* out_re = (float*)d_out;
    float* out_im = out_re + n;

    k_stats1<<<NBLK, NTHR>>>(w_re, w_im, n);
    k_reduce<<<1, NTHR>>>(0);
    k_step2<<<NBLK, NTHR>>>(w_re, w_im, temp, n);
    k_reduce<<<1, NTHR>>>(2);
    k_final<<<NBLK, NTHR>>>(w_re, w_im, temp, out_re, out_im, n);
}